// round 7
// baseline (speedup 1.0000x reference)
#include <cuda_runtime.h>
#include <cstdint>

#define D 128
#define NVOX (D * D * D)
#define P 130
#define PV (P * P * P)
#define FULL 0xFFFFFFFFu
#define NSLAB 128

// zero-padded SoA (e0,e1,e2,state0). Shell entries are NEVER written:
// static zero-init provides jnp.pad semantics permanently.
__device__ float4 g_pack[PV];
__device__ int    g_cnt[NSLAB];   // per-slab phase-A completion counters

__global__ void __launch_bounds__(256)
ca_fused_kernel(const float* __restrict__ x,
                const float* __restrict__ out,
                float* __restrict__ y)
{
    __shared__ __align__(16) float ly[256 * 5];

    const int tid  = threadIdx.x;
    const int bid  = blockIdx.x;
    const int base = bid * 256;
    const int v    = base + tid;
    const int lane = tid & 31;

    const int k = v & (D - 1);
    const int j = (v >> 7) & (D - 1);
    const int i = v >> 14;            // == bid >> 6, constant per block
    const int pc = ((i + 1) * P + (j + 1)) * P + (k + 1);

    // ---------- phase A: transpose own chunk into padded pack ----------
    const float* xv = x + (size_t)v * 5;
    float s0f = xv[0];
    float e0  = xv[1];
    float e1  = xv[2];
    float e2  = xv[3];
    g_pack[pc] = make_float4(e0, e1, e2, s0f);

    // independent streaming loads overlap with the fence/arrive below
    const float4* o4 = reinterpret_cast<const float4*>(out + (size_t)v * 8);
    float4 oa = o4[0];
    float4 ob = o4[1];

    __threadfence();          // publish pack writes
    __syncthreads();          // all threads of block done writing+fencing
    if (tid == 0) atomicAdd(&g_cnt[i], 1);

    // ---------- local (gather-free) part of the update ----------
    int   state1 = 0;
    float bst    = oa.x;
    if (oa.y > bst) { bst = oa.y; state1 = 1; }
    if (oa.z > bst) { bst = oa.z; state1 = 2; }
    if (oa.w > bst) { bst = oa.w; state1 = 3; }

    int state0 = (int)s0f;
    if (state0 == 0) state1 = 0;

    float y_e0 = e0, y_e1 = e1, y_e2 = e2;
    float field1 = ob.w;
    if (state1 <= 1) {
        field1 = -1.0f;
        y_e0 = -1.0f; y_e1 = -1.0f; y_e2 = -1.0f;
    } else if (state1 == 2) {
        field1 = fminf(fmaxf(field1, 0.0f), 0.92f);
    } else {
        field1 = 1.0f;
    }

    // ---------- phase B: cooperative gather (needs slabs i-1..i+1) ----------
    bool flag = (state0 <= 1) && (state1 > 1);
    unsigned mask = __ballot_sync(FULL, flag);

    if (mask) {
        if (lane == 0) {
            int lo = (i > 0)         ? i - 1 : i;
            int hi = (i < NSLAB - 1) ? i + 1 : i;
            for (int s = lo; s <= hi; s++) {
                while (((volatile int*)g_cnt)[s] < 64) __nanosleep(200);
            }
        }
        __syncwarp();
        __threadfence();      // acquire: pack writes of producers visible

        int c26 = lane + (lane >= 13 ? 1 : 0);
        int di = c26 / 9 - 1;
        int dj = (c26 / 3) % 3 - 1;
        int dk = c26 % 3 - 1;
        int noff = (di * P + dj) * P + dk;

        while (mask) {
            int src = __ffs(mask) - 1;
            mask &= mask - 1;

            int   spc = __shfl_sync(FULL, pc,   src);
            float rx  = __shfl_sync(FULL, ob.x, src);
            float ry  = __shfl_sync(FULL, ob.y, src);
            float rz  = __shfl_sync(FULL, ob.z, src);

            float n0 = 0.0f, n1 = 0.0f, n2 = 0.0f;
            if (lane < 26) {
                float4 nb = g_pack[spc + noff];   // one LDG.128
                n0 = nb.x; n1 = nb.y; n2 = nb.z;
            }
            float d0 = n0 - rx;
            float d1 = n1 - ry;
            float d2 = n2 - rz;
            float dist = d0 * d0 + d1 * d1 + d2 * d2;

            unsigned bits = (lane < 26) ? __float_as_uint(dist) : 0xFFFFFFFFu;
            unsigned dmin = __reduce_min_sync(FULL, bits);
            unsigned win  = __ballot_sync(FULL, bits == dmin);
            int s = __ffs(win) - 1;

            float w0 = __shfl_sync(FULL, n0, s);
            float w1 = __shfl_sync(FULL, n1, s);
            float w2 = __shfl_sync(FULL, n2, s);
            if (lane == src) { y_e0 = w0; y_e1 = w1; y_e2 = w2; }
        }
    }

    // ---------- staged coalesced float4 output ----------
    ly[tid * 5 + 0] = (float)state1;
    ly[tid * 5 + 1] = y_e0;
    ly[tid * 5 + 2] = y_e1;
    ly[tid * 5 + 3] = y_e2;
    ly[tid * 5 + 4] = field1;
    __syncthreads();
    {
        float4* yb = reinterpret_cast<float4*>(y + (size_t)base * 5);
        const float4* s4 = reinterpret_cast<const float4*>(ly);
        #pragma unroll
        for (int t = tid; t < 256 * 5 / 4; t += 256) yb[t] = s4[t];
    }
}

extern "C" void kernel_launch(void* const* d_in, const int* in_sizes, int n_in,
                              void* d_out, int out_size)
{
    const float* x   = (const float*)d_in[0];
    const float* out = (const float*)d_in[1];
    if (n_in >= 2 && in_sizes[0] == 8 * NVOX && in_sizes[1] == 5 * NVOX) {
        const float* t = x; x = out; out = t;
    }
    float* y = (float*)d_out;

    void* cnt_addr = nullptr;
    cudaGetSymbolAddress(&cnt_addr, g_cnt);
    cudaMemsetAsync(cnt_addr, 0, NSLAB * sizeof(int));

    ca_fused_kernel<<<NVOX / 256, 256>>>(x, out, y);
}

// round 8
// speedup vs baseline: 2.9889x; 2.9889x over previous
#include <cuda_runtime.h>
#include <cstdint>

#define D 128
#define NVOX (D * D * D)
#define P 130
#define PV (P * P * P)
#define FULL 0xFFFFFFFFu
#define NCHUNK 8
#define SPC (D / NCHUNK)          // 16 interior slabs per chunk

// zero-padded SoA: (e0, e1, e2, state0) per voxel; shell written as zeros
__device__ float4 g_pack[PV];

// ---------- pass 1 chunk: padded slabs pi in [pi_base, pi_base+n_pi) ----------
__global__ void __launch_bounds__(256)
transpose_kernel(const float* __restrict__ x, int pi_base, int n_pi)
{
    int idx = blockIdx.x * blockDim.x + threadIdx.x;
    if (idx >= n_pi * P * P) return;
    int pv = pi_base * P * P + idx;

    int pk = pv % P;
    int t  = pv / P;
    int pj = t % P;
    int pi = t / P;

    int i = pi - 1, j = pj - 1, k = pk - 1;
    float4 r = make_float4(0.0f, 0.0f, 0.0f, 0.0f);
    if (((unsigned)i < (unsigned)D) &
        ((unsigned)j < (unsigned)D) &
        ((unsigned)k < (unsigned)D)) {
        const float* xv = x + (((long)i * D + j) * D + k) * 5;
        r.x = xv[1];
        r.y = xv[2];
        r.z = xv[3];
        r.w = xv[0];
    }
    g_pack[pv] = r;
}

// ---------- pass 2 chunk: interior voxels v in [v_base, v_base + n) ----------
__global__ void __launch_bounds__(256)
ca_update_kernel(const float* __restrict__ out, float* __restrict__ y, int v_base)
{
    __shared__ __align__(16) float ly[256 * 5];

    const int tid  = threadIdx.x;
    const int base = v_base + blockIdx.x * 256;
    const int v    = base + tid;
    const int lane = tid & 31;

    const int k = v & (D - 1);
    const int j = (v >> 7) & (D - 1);
    const int i = v >> 14;
    const int pc = ((i + 1) * P + (j + 1)) * P + (k + 1);

    const float4* o4 = reinterpret_cast<const float4*>(out + (size_t)v * 8);
    float4 oa = o4[0];
    float4 ob = o4[1];

    int   state1 = 0;
    float bst    = oa.x;
    if (oa.y > bst) { bst = oa.y; state1 = 1; }
    if (oa.z > bst) { bst = oa.z; state1 = 2; }
    if (oa.w > bst) { bst = oa.w; state1 = 3; }

    float4 ctr = g_pack[pc];
    int state0 = (int)ctr.w;
    if (state0 == 0) state1 = 0;

    float y_e0 = ctr.x;
    float y_e1 = ctr.y;
    float y_e2 = ctr.z;

    float field1 = ob.w;
    if (state1 <= 1) {
        field1 = -1.0f;
        y_e0 = -1.0f; y_e1 = -1.0f; y_e2 = -1.0f;
    } else if (state1 == 2) {
        field1 = fminf(fmaxf(field1, 0.0f), 0.92f);
    } else {
        field1 = 1.0f;
    }

    // warp-cooperative 26-neighbor argmin (lex order, first occurrence)
    bool flag = (state0 <= 1) && (state1 > 1);
    unsigned mask = __ballot_sync(FULL, flag);

    int c26 = lane + (lane >= 13 ? 1 : 0);
    int di = c26 / 9 - 1;
    int dj = (c26 / 3) % 3 - 1;
    int dk = c26 % 3 - 1;
    int noff = (di * P + dj) * P + dk;

    while (mask) {
        int src = __ffs(mask) - 1;
        mask &= mask - 1;

        int   spc = __shfl_sync(FULL, pc,   src);
        float rx  = __shfl_sync(FULL, ob.x, src);
        float ry  = __shfl_sync(FULL, ob.y, src);
        float rz  = __shfl_sync(FULL, ob.z, src);

        float n0 = 0.0f, n1 = 0.0f, n2 = 0.0f;
        if (lane < 26) {
            float4 nb = g_pack[spc + noff];   // single LDG.128
            n0 = nb.x; n1 = nb.y; n2 = nb.z;
        }
        float d0 = n0 - rx;
        float d1 = n1 - ry;
        float d2 = n2 - rz;
        float dist = d0 * d0 + d1 * d1 + d2 * d2;

        unsigned bits = (lane < 26) ? __float_as_uint(dist) : 0xFFFFFFFFu;
        unsigned dmin = __reduce_min_sync(FULL, bits);
        unsigned win  = __ballot_sync(FULL, bits == dmin);
        int s = __ffs(win) - 1;

        float w0 = __shfl_sync(FULL, n0, s);
        float w1 = __shfl_sync(FULL, n1, s);
        float w2 = __shfl_sync(FULL, n2, s);
        if (lane == src) { y_e0 = w0; y_e1 = w1; y_e2 = w2; }
    }

    // staged coalesced float4 output
    ly[tid * 5 + 0] = (float)state1;
    ly[tid * 5 + 1] = y_e0;
    ly[tid * 5 + 2] = y_e1;
    ly[tid * 5 + 3] = y_e2;
    ly[tid * 5 + 4] = field1;
    __syncthreads();
    {
        float4* yb = reinterpret_cast<float4*>(y + (size_t)(base) * 5);
        const float4* s4 = reinterpret_cast<const float4*>(ly);
        #pragma unroll
        for (int t = tid; t < 256 * 5 / 4; t += 256) yb[t] = s4[t];
    }
}

extern "C" void kernel_launch(void* const* d_in, const int* in_sizes, int n_in,
                              void* d_out, int out_size)
{
    const float* x   = (const float*)d_in[0];
    const float* out = (const float*)d_in[1];
    if (n_in >= 2 && in_sizes[0] == 8 * NVOX && in_sizes[1] == 5 * NVOX) {
        const float* t = x; x = out; out = t;
    }
    float* y = (float*)d_out;

    static cudaStream_t s1;
    static cudaEvent_t evp[NCHUNK], ev_fork, ev_join;
    static bool inited = false;
    if (!inited) {
        cudaStreamCreateWithFlags(&s1, cudaStreamNonBlocking);
        for (int c = 0; c < NCHUNK; c++)
            cudaEventCreateWithFlags(&evp[c], cudaEventDisableTiming);
        cudaEventCreateWithFlags(&ev_fork, cudaEventDisableTiming);
        cudaEventCreateWithFlags(&ev_join, cudaEventDisableTiming);
        inited = true;
    }

    // fork s1 from the (possibly capturing) default stream
    cudaEventRecord(ev_fork, 0);
    cudaStreamWaitEvent(s1, ev_fork, 0);

    // pass 1 chunks on default stream, event after each
    for (int c = 0; c < NCHUNK; c++) {
        int lo = (c == 0) ? 0 : 1 + SPC * c;                 // padded pi start
        int hi = (c == NCHUNK - 1) ? P : 1 + SPC * (c + 1);  // padded pi end
        int n_pi  = hi - lo;
        int total = n_pi * P * P;
        transpose_kernel<<<(total + 255) / 256, 256>>>(x, lo, n_pi);
        cudaEventRecord(evp[c], 0);
    }

    // pass 2 chunks on s1; chunk c needs pass1 chunks <= c+1
    for (int c = 0; c < NCHUNK; c++) {
        int dep = (c + 1 < NCHUNK) ? c + 1 : NCHUNK - 1;
        cudaStreamWaitEvent(s1, evp[dep], 0);
        int v_base = c * SPC * D * D;
        ca_update_kernel<<<SPC * D * D / 256, 256, 0, s1>>>(out, y, v_base);
    }

    // join back into the default (capture) stream
    cudaEventRecord(ev_join, s1);
    cudaStreamWaitEvent(0, ev_join, 0);
}

// round 9
// speedup vs baseline: 3.7485x; 1.2541x over previous
#include <cuda_runtime.h>
#include <cstdint>

#define D 128
#define NVOX (D * D * D)
#define P 130
#define PV (P * P * P)
#define FULL 0xFFFFFFFFu
#define NCHUNK 4
#define SPC (D / NCHUNK)          // 32 interior slabs per p2 chunk

// zero-padded SoA: (e0, e1, e2, state0) per voxel; shell written as zeros
__device__ float4 g_pack[PV];

// ---------- pass 1 chunk: padded slabs pi in [pi_base, pi_base+n_pi) ----------
__global__ void __launch_bounds__(256)
transpose_kernel(const float* __restrict__ x, int pi_base, int n_pi)
{
    int idx = blockIdx.x * blockDim.x + threadIdx.x;
    if (idx >= n_pi * P * P) return;
    int pv = pi_base * P * P + idx;

    int pk = pv % P;
    int t  = pv / P;
    int pj = t % P;
    int pi = t / P;

    int i = pi - 1, j = pj - 1, k = pk - 1;
    float4 r = make_float4(0.0f, 0.0f, 0.0f, 0.0f);
    if (((unsigned)i < (unsigned)D) &
        ((unsigned)j < (unsigned)D) &
        ((unsigned)k < (unsigned)D)) {
        const float* xv = x + (((long)i * D + j) * D + k) * 5;
        r.x = xv[1];
        r.y = xv[2];
        r.z = xv[3];
        r.w = xv[0];
    }
    g_pack[pv] = r;
}

// ---------- pass 2 chunk: interior voxels v in [v_base, v_base + n) ----------
__global__ void __launch_bounds__(256)
ca_update_kernel(const float* __restrict__ out, float* __restrict__ y, int v_base)
{
    __shared__ __align__(16) float ly[256 * 5];

    const int tid  = threadIdx.x;
    const int base = v_base + blockIdx.x * 256;
    const int v    = base + tid;
    const int lane = tid & 31;

    const int k = v & (D - 1);
    const int j = (v >> 7) & (D - 1);
    const int i = v >> 14;
    const int pc = ((i + 1) * P + (j + 1)) * P + (k + 1);

    // streaming loads of out: evict-first, keep g_pack resident in L2
    const float4* o4 = reinterpret_cast<const float4*>(out + (size_t)v * 8);
    float4 oa = __ldcs(o4 + 0);
    float4 ob = __ldcs(o4 + 1);

    int   state1 = 0;
    float bst    = oa.x;
    if (oa.y > bst) { bst = oa.y; state1 = 1; }
    if (oa.z > bst) { bst = oa.z; state1 = 2; }
    if (oa.w > bst) { bst = oa.w; state1 = 3; }

    float4 ctr = g_pack[pc];
    int state0 = (int)ctr.w;
    if (state0 == 0) state1 = 0;

    float y_e0 = ctr.x;
    float y_e1 = ctr.y;
    float y_e2 = ctr.z;

    float field1 = ob.w;
    if (state1 <= 1) {
        field1 = -1.0f;
        y_e0 = -1.0f; y_e1 = -1.0f; y_e2 = -1.0f;
    } else if (state1 == 2) {
        field1 = fminf(fmaxf(field1, 0.0f), 0.92f);
    } else {
        field1 = 1.0f;
    }

    // warp-cooperative 26-neighbor argmin (lex order, first occurrence)
    bool flag = (state0 <= 1) && (state1 > 1);
    unsigned mask = __ballot_sync(FULL, flag);

    int c26 = lane + (lane >= 13 ? 1 : 0);
    int di = c26 / 9 - 1;
    int dj = (c26 / 3) % 3 - 1;
    int dk = c26 % 3 - 1;
    int noff = (di * P + dj) * P + dk;

    while (mask) {
        int src = __ffs(mask) - 1;
        mask &= mask - 1;

        int   spc = __shfl_sync(FULL, pc,   src);
        float rx  = __shfl_sync(FULL, ob.x, src);
        float ry  = __shfl_sync(FULL, ob.y, src);
        float rz  = __shfl_sync(FULL, ob.z, src);

        float n0 = 0.0f, n1 = 0.0f, n2 = 0.0f;
        if (lane < 26) {
            float4 nb = g_pack[spc + noff];   // single LDG.128, L2-resident
            n0 = nb.x; n1 = nb.y; n2 = nb.z;
        }
        float d0 = n0 - rx;
        float d1 = n1 - ry;
        float d2 = n2 - rz;
        float dist = d0 * d0 + d1 * d1 + d2 * d2;

        unsigned bits = (lane < 26) ? __float_as_uint(dist) : 0xFFFFFFFFu;
        unsigned dmin = __reduce_min_sync(FULL, bits);
        unsigned win  = __ballot_sync(FULL, bits == dmin);
        int s = __ffs(win) - 1;

        float w0 = __shfl_sync(FULL, n0, s);
        float w1 = __shfl_sync(FULL, n1, s);
        float w2 = __shfl_sync(FULL, n2, s);
        if (lane == src) { y_e0 = w0; y_e1 = w1; y_e2 = w2; }
    }

    // staged coalesced float4 output (streaming stores)
    ly[tid * 5 + 0] = (float)state1;
    ly[tid * 5 + 1] = y_e0;
    ly[tid * 5 + 2] = y_e1;
    ly[tid * 5 + 3] = y_e2;
    ly[tid * 5 + 4] = field1;
    __syncthreads();
    {
        float4* yb = reinterpret_cast<float4*>(y + (size_t)base * 5);
        const float4* s4 = reinterpret_cast<const float4*>(ly);
        #pragma unroll
        for (int t = tid; t < 256 * 5 / 4; t += 256) __stcs(yb + t, s4[t]);
    }
}

extern "C" void kernel_launch(void* const* d_in, const int* in_sizes, int n_in,
                              void* d_out, int out_size)
{
    const float* x   = (const float*)d_in[0];
    const float* out = (const float*)d_in[1];
    if (n_in >= 2 && in_sizes[0] == 8 * NVOX && in_sizes[1] == 5 * NVOX) {
        const float* t = x; x = out; out = t;
    }
    float* y = (float*)d_out;

    static cudaStream_t s1;
    static cudaEvent_t evp[NCHUNK], ev_fork, ev_join;
    static bool inited = false;
    if (!inited) {
        cudaStreamCreateWithFlags(&s1, cudaStreamNonBlocking);
        for (int c = 0; c < NCHUNK; c++)
            cudaEventCreateWithFlags(&evp[c], cudaEventDisableTiming);
        cudaEventCreateWithFlags(&ev_fork, cudaEventDisableTiming);
        cudaEventCreateWithFlags(&ev_join, cudaEventDisableTiming);
        inited = true;
    }

    // fork s1 from the capture stream
    cudaEventRecord(ev_fork, 0);
    cudaStreamWaitEvent(s1, ev_fork, 0);

    // pass-1 chunks on default stream. Chunk c covers padded pi:
    //   c=0: [0, 34)   c=1: [34, 67)   c=2: [67, 100)   c=3: [100, 130)
    // p2 chunk c needs pi <= 32c+33, satisfied by p1 chunks <= c.
    const int p1_lo[NCHUNK + 1] = {0, 34, 67, 100, 130};
    for (int c = 0; c < NCHUNK; c++) {
        int lo = p1_lo[c], n_pi = p1_lo[c + 1] - lo;
        int total = n_pi * P * P;
        transpose_kernel<<<(total + 255) / 256, 256>>>(x, lo, n_pi);
        cudaEventRecord(evp[c], 0);
    }

    // pass-2 chunks on s1
    for (int c = 0; c < NCHUNK; c++) {
        cudaStreamWaitEvent(s1, evp[c], 0);
        int v_base = c * SPC * D * D;
        ca_update_kernel<<<SPC * D * D / 256, 256, 0, s1>>>(out, y, v_base);
    }

    // join back into the capture stream
    cudaEventRecord(ev_join, s1);
    cudaStreamWaitEvent(0, ev_join, 0);
}

// round 10
// speedup vs baseline: 4.4713x; 1.1929x over previous
#include <cuda_runtime.h>
#include <cstdint>

#define D 128
#define NVOX (D * D * D)
#define P 130
#define PV (P * P * P)
#define FULL 0xFFFFFFFFu

// zero-padded SoA: (e0, e1, e2, state0). Shell entries are NEVER written;
// static zero-init provides jnp.pad semantics permanently.
__device__ float4 g_pack[PV];

// ---------- pass 1: smem-staged transpose, interior only ----------
__global__ void __launch_bounds__(256)
transpose_kernel(const float* __restrict__ x)
{
    __shared__ __align__(16) float sx[256 * 5];
    const int tid  = threadIdx.x;
    const int base = blockIdx.x * 256;

    const float4* xb = reinterpret_cast<const float4*>(x + (size_t)base * 5);
    float4* s4 = reinterpret_cast<float4*>(sx);
    #pragma unroll
    for (int t = tid; t < 320; t += 256) s4[t] = xb[t];
    __syncthreads();

    const int v = base + tid;
    const int k = v & (D - 1);
    const int j = (v >> 7) & (D - 1);
    const int i = v >> 14;
    const int pc = ((i + 1) * P + (j + 1)) * P + (k + 1);

    g_pack[pc] = make_float4(sx[tid * 5 + 1], sx[tid * 5 + 2],
                             sx[tid * 5 + 3], sx[tid * 5 + 0]);
}

// ---------- pass 2: tiled update with smem float4 halo ----------
__global__ void __launch_bounds__(512)
ca_update_kernel(const float* __restrict__ out, float* __restrict__ y)
{
    __shared__ __align__(16) float4 sh[1000];      // 10^3 halo of pack
    __shared__ __align__(16) float  ly[512 * 5];   // output staging

    const int tid  = threadIdx.x;
    const int lane = tid & 31;
    const int i0 = blockIdx.z * 8;
    const int j0 = blockIdx.y * 8;
    const int k0 = blockIdx.x * 8;

    // halo load: padded base (i0, j0, k0); rows are contiguous float4 runs
    for (int h = tid; h < 1000; h += 512) {
        int hk = h % 10;
        int t  = h / 10;
        int hj = t % 10;
        int hi = t / 10;
        sh[h] = g_pack[((i0 + hi) * P + (j0 + hj)) * P + (k0 + hk)];
    }
    __syncthreads();

    const int li = tid >> 6;
    const int lj = (tid >> 3) & 7;
    const int lk = tid & 7;
    const int v  = (((i0 + li) * D + (j0 + lj)) * D + (k0 + lk));
    const int cb = (li + 1) * 100 + (lj + 1) * 10 + (lk + 1);

    const float4* o4 = reinterpret_cast<const float4*>(out + (size_t)v * 8);
    float4 oa = __ldcs(o4 + 0);
    float4 ob = __ldcs(o4 + 1);

    int   state1 = 0;
    float bst    = oa.x;
    if (oa.y > bst) { bst = oa.y; state1 = 1; }
    if (oa.z > bst) { bst = oa.z; state1 = 2; }
    if (oa.w > bst) { bst = oa.w; state1 = 3; }

    float4 ctr = sh[cb];
    int state0 = (int)ctr.w;
    if (state0 == 0) state1 = 0;

    float y_e0 = ctr.x;
    float y_e1 = ctr.y;
    float y_e2 = ctr.z;

    float field1 = ob.w;
    if (state1 <= 1) {
        field1 = -1.0f;
        y_e0 = -1.0f; y_e1 = -1.0f; y_e2 = -1.0f;
    } else if (state1 == 2) {
        field1 = fminf(fmaxf(field1, 0.0f), 0.92f);
    } else {
        field1 = 1.0f;
    }

    // warp-cooperative 26-neighbor argmin from smem (lex order, first occ.)
    bool flag = (state0 <= 1) && (state1 > 1);
    unsigned mask = __ballot_sync(FULL, flag);

    int c26 = lane + (lane >= 13 ? 1 : 0);
    int di = c26 / 9 - 1;
    int dj = (c26 / 3) % 3 - 1;
    int dk = c26 % 3 - 1;
    int noff = di * 100 + dj * 10 + dk;

    while (mask) {
        int src = __ffs(mask) - 1;
        mask &= mask - 1;

        int   scb = __shfl_sync(FULL, cb,   src);
        float rx  = __shfl_sync(FULL, ob.x, src);
        float ry  = __shfl_sync(FULL, ob.y, src);
        float rz  = __shfl_sync(FULL, ob.z, src);

        float n0 = 0.0f, n1 = 0.0f, n2 = 0.0f;
        if (lane < 26) {
            float4 nb = sh[scb + noff];        // LDS.128
            n0 = nb.x; n1 = nb.y; n2 = nb.z;
        }
        float d0 = n0 - rx;
        float d1 = n1 - ry;
        float d2 = n2 - rz;
        float dist = d0 * d0 + d1 * d1 + d2 * d2;

        unsigned bits = (lane < 26) ? __float_as_uint(dist) : 0xFFFFFFFFu;
        unsigned dmin = __reduce_min_sync(FULL, bits);
        unsigned win  = __ballot_sync(FULL, bits == dmin);
        int s = __ffs(win) - 1;

        float w0 = __shfl_sync(FULL, n0, s);
        float w1 = __shfl_sync(FULL, n1, s);
        float w2 = __shfl_sync(FULL, n2, s);
        if (lane == src) { y_e0 = w0; y_e1 = w1; y_e2 = w2; }
    }

    // staged coalesced float4 output
    ly[tid * 5 + 0] = (float)state1;
    ly[tid * 5 + 1] = y_e0;
    ly[tid * 5 + 2] = y_e1;
    ly[tid * 5 + 3] = y_e2;
    ly[tid * 5 + 4] = field1;
    __syncthreads();

    // 64 (li,lj) rows x 10 float4 (base 16B-aligned: k0 % 8 == 0)
    for (int f = tid; f < 640; f += 512) {
        int row  = f / 10;
        int part = f - row * 10;
        int ri = i0 + (row >> 3);
        int rj = j0 + (row & 7);
        long gbase = (((long)ri * D + rj) * D + k0) * 5 + part * 4;
        __stcs(reinterpret_cast<float4*>(y + gbase),
               *reinterpret_cast<const float4*>(&ly[row * 40 + part * 4]));
    }
}

extern "C" void kernel_launch(void* const* d_in, const int* in_sizes, int n_in,
                              void* d_out, int out_size)
{
    const float* x   = (const float*)d_in[0];
    const float* out = (const float*)d_in[1];
    if (n_in >= 2 && in_sizes[0] == 8 * NVOX && in_sizes[1] == 5 * NVOX) {
        const float* t = x; x = out; out = t;
    }
    float* y = (float*)d_out;

    transpose_kernel<<<NVOX / 256, 256>>>(x);
    dim3 grid(D / 8, D / 8, D / 8);
    ca_update_kernel<<<grid, 512>>>(out, y);
}

// round 11
// speedup vs baseline: 4.8542x; 1.0856x over previous
#include <cuda_runtime.h>
#include <cstdint>

#define D 128
#define NVOX (D * D * D)
#define P 130
#define PV (P * P * P)
#define FULL 0xFFFFFFFFu

// zero-padded SoA: (e0, e1, e2, state0) per voxel; shell written as zeros
__device__ float4 g_pack[PV];

// ---------- pass 1: padded transpose (monolithic, LTS-capped) ----------
__global__ void __launch_bounds__(256)
transpose_kernel(const float* __restrict__ x)
{
    int pv = blockIdx.x * blockDim.x + threadIdx.x;
    if (pv >= PV) return;

    int pk = pv % P;
    int t  = pv / P;
    int pj = t % P;
    int pi = t / P;

    int i = pi - 1, j = pj - 1, k = pk - 1;
    float4 r = make_float4(0.0f, 0.0f, 0.0f, 0.0f);
    if (((unsigned)i < (unsigned)D) &
        ((unsigned)j < (unsigned)D) &
        ((unsigned)k < (unsigned)D)) {
        const float* xv = x + (((long)i * D + j) * D + k) * 5;
        r.x = xv[1];
        r.y = xv[2];
        r.z = xv[3];
        r.w = xv[0];
    }
    g_pack[pv] = r;
}

// ---------- pass 2: update with MLP-2 cooperative gather ----------
__global__ void __launch_bounds__(256)
ca_update_kernel(const float* __restrict__ out, float* __restrict__ y)
{
    __shared__ __align__(16) float ly[256 * 5];

    const int tid  = threadIdx.x;
    const int base = blockIdx.x * 256;
    const int v    = base + tid;
    const int lane = tid & 31;

    const int k = v & (D - 1);
    const int j = (v >> 7) & (D - 1);
    const int i = v >> 14;
    const int pc = ((i + 1) * P + (j + 1)) * P + (k + 1);

    const float4* o4 = reinterpret_cast<const float4*>(out + (size_t)v * 8);
    float4 oa = __ldcs(o4 + 0);
    float4 ob = __ldcs(o4 + 1);

    int   state1 = 0;
    float bst    = oa.x;
    if (oa.y > bst) { bst = oa.y; state1 = 1; }
    if (oa.z > bst) { bst = oa.z; state1 = 2; }
    if (oa.w > bst) { bst = oa.w; state1 = 3; }

    float4 ctr = g_pack[pc];
    int state0 = (int)ctr.w;
    if (state0 == 0) state1 = 0;

    float y_e0 = ctr.x;
    float y_e1 = ctr.y;
    float y_e2 = ctr.z;

    float field1 = ob.w;
    if (state1 <= 1) {
        field1 = -1.0f;
        y_e0 = -1.0f; y_e1 = -1.0f; y_e2 = -1.0f;
    } else if (state1 == 2) {
        field1 = fminf(fmaxf(field1, 0.0f), 0.92f);
    } else {
        field1 = 1.0f;
    }

    // warp-cooperative 26-neighbor argmin, two voxels in flight (MLP 2)
    bool flag = (state0 <= 1) && (state1 > 1);
    unsigned mask = __ballot_sync(FULL, flag);

    int c26 = lane + (lane >= 13 ? 1 : 0);
    int di = c26 / 9 - 1;
    int dj = (c26 / 3) % 3 - 1;
    int dk = c26 % 3 - 1;
    int noff = (di * P + dj) * P + dk;
    const bool gl = (lane < 26);

    while (mask) {
        int srcA = __ffs(mask) - 1;
        mask &= mask - 1;
        int srcB = -1;
        if (mask) { srcB = __ffs(mask) - 1; mask &= mask - 1; }

        int spcA = __shfl_sync(FULL, pc, srcA);
        int spcB = __shfl_sync(FULL, pc, srcB < 0 ? srcA : srcB);

        // both scattered loads issued before any dependent reduction
        float4 nbA = make_float4(0.f, 0.f, 0.f, 0.f);
        float4 nbB = make_float4(0.f, 0.f, 0.f, 0.f);
        if (gl) {
            nbA = g_pack[spcA + noff];
            if (srcB >= 0) nbB = g_pack[spcB + noff];
        }

        float rxA = __shfl_sync(FULL, ob.x, srcA);
        float ryA = __shfl_sync(FULL, ob.y, srcA);
        float rzA = __shfl_sync(FULL, ob.z, srcA);

        {
            float d0 = nbA.x - rxA, d1 = nbA.y - ryA, d2 = nbA.z - rzA;
            float dist = d0 * d0 + d1 * d1 + d2 * d2;
            unsigned key = gl ? ((__float_as_uint(dist) & ~31u) | lane)
                              : 0xFFFFFFFFu;
            unsigned kmin = __reduce_min_sync(FULL, key);
            int s = (int)(kmin & 31u);
            float w0 = __shfl_sync(FULL, nbA.x, s);
            float w1 = __shfl_sync(FULL, nbA.y, s);
            float w2 = __shfl_sync(FULL, nbA.z, s);
            if (lane == srcA) { y_e0 = w0; y_e1 = w1; y_e2 = w2; }
        }

        if (srcB >= 0) {
            float rxB = __shfl_sync(FULL, ob.x, srcB);
            float ryB = __shfl_sync(FULL, ob.y, srcB);
            float rzB = __shfl_sync(FULL, ob.z, srcB);
            float d0 = nbB.x - rxB, d1 = nbB.y - ryB, d2 = nbB.z - rzB;
            float dist = d0 * d0 + d1 * d1 + d2 * d2;
            unsigned key = gl ? ((__float_as_uint(dist) & ~31u) | lane)
                              : 0xFFFFFFFFu;
            unsigned kmin = __reduce_min_sync(FULL, key);
            int s = (int)(kmin & 31u);
            float w0 = __shfl_sync(FULL, nbB.x, s);
            float w1 = __shfl_sync(FULL, nbB.y, s);
            float w2 = __shfl_sync(FULL, nbB.z, s);
            if (lane == srcB) { y_e0 = w0; y_e1 = w1; y_e2 = w2; }
        }
    }

    // staged coalesced float4 output (streaming stores)
    ly[tid * 5 + 0] = (float)state1;
    ly[tid * 5 + 1] = y_e0;
    ly[tid * 5 + 2] = y_e1;
    ly[tid * 5 + 3] = y_e2;
    ly[tid * 5 + 4] = field1;
    __syncthreads();
    {
        float4* yb = reinterpret_cast<float4*>(y + (size_t)base * 5);
        const float4* s4 = reinterpret_cast<const float4*>(ly);
        #pragma unroll
        for (int t = tid; t < 320; t += 256) __stcs(yb + t, s4[t]);
    }
}

extern "C" void kernel_launch(void* const* d_in, const int* in_sizes, int n_in,
                              void* d_out, int out_size)
{
    const float* x   = (const float*)d_in[0];
    const float* out = (const float*)d_in[1];
    if (n_in >= 2 && in_sizes[0] == 8 * NVOX && in_sizes[1] == 5 * NVOX) {
        const float* t = x; x = out; out = t;
    }
    float* y = (float*)d_out;

    transpose_kernel<<<(PV + 255) / 256, 256>>>(x);
    ca_update_kernel<<<NVOX / 256, 256>>>(out, y);
}